// round 13
// baseline (speedup 1.0000x reference)
#include <cuda_runtime.h>
#include <math.h>
#include <stdint.h>

// Problem dims
#define B_  2
#define S_  2048
#define D_  1024
#define H_  16
#define DH_ 64
#define M_  4096
#define R_  (B_*S_)   // 4096 rows total

// ---------------- scratch (__device__ globals: allocation-free) ----------------
__device__ float g_h    [(size_t)R_*D_];
__device__ float g_q    [(size_t)R_*D_];
__device__ float g_k    [(size_t)R_*D_];
__device__ float g_v    [(size_t)R_*D_];
__device__ float g_ctx  [(size_t)R_*D_];
__device__ float g_mlpin[(size_t)R_*D_];
__device__ float g_h2   [(size_t)R_*D_];
__device__ float g_ff1  [(size_t)R_*M_];
// rounded weights: wq(1M) wk(1M) wv(1M) wo(1M) w1(4M) w2(4M) = 12M floats
__device__ float g_wr   [(size_t)12*1024*1024];

#define WR_WQ 0
#define WR_WK (1024*1024)
#define WR_WV (2*1024*1024)
#define WR_WO (3*1024*1024)
#define WR_W1 (4*1024*1024)
#define WR_W2 (8*1024*1024)

// ---------------- helpers ----------------
__device__ __forceinline__ float gelu_f(float x){
    const float c = 0.7978845608028654f;  // sqrt(2/pi)
    return 0.5f * x * (1.0f + tanhf(c * (x + 0.044715f * x * x * x)));
}

__device__ __forceinline__ float tf(float x){
    uint32_t u;
    asm("cvt.rna.tf32.f32 %0, %1;" : "=r"(u) : "f"(x));
    return __uint_as_float(u);
}

__device__ __forceinline__ float ex2f(float x){
    float y; asm("ex2.approx.ftz.f32 %0, %1;" : "=f"(y) : "f"(x)); return y;
}

__device__ __forceinline__ void mma_tf32(float* c, const uint32_t* a, const uint32_t* b){
    asm volatile(
        "mma.sync.aligned.m16n8k8.row.col.f32.tf32.tf32.f32 "
        "{%0,%1,%2,%3}, {%4,%5,%6,%7}, {%8,%9}, {%0,%1,%2,%3};"
        : "+f"(c[0]), "+f"(c[1]), "+f"(c[2]), "+f"(c[3])
        : "r"(a[0]), "r"(a[1]), "r"(a[2]), "r"(a[3]), "r"(b[0]), "r"(b[1]));
}

__device__ __forceinline__ void cpa16(uint32_t dst, const void* src){
    asm volatile("cp.async.cg.shared.global [%0], [%1], 16;" :: "r"(dst), "l"(src));
}

// ---------------- weight pre-round (RNA tf32) ----------------
__global__ __launch_bounds__(256) void roundw_k(const float* __restrict__ w,
                                               float* __restrict__ d, int n4)
{
    int i = blockIdx.x * blockDim.x + threadIdx.x;
    int stride = gridDim.x * blockDim.x;
    for (; i < n4; i += stride) {
        float4 v = ((const float4*)w)[i];
        v.x = tf(v.x); v.y = tf(v.y); v.z = tf(v.z); v.w = tf(v.w);
        ((float4*)d)[i] = v;
    }
}

// ---------------- LayerNorm (output RNA-rounded: feeds MMAs only) ----------------
__global__ __launch_bounds__(256) void layernorm_k(
    const float* __restrict__ x, const float* __restrict__ s,
    const float* __restrict__ b, float* __restrict__ y)
{
    size_t row = blockIdx.x;
    int t = threadIdx.x;
    const float4* xr = (const float4*)(x + row * (size_t)D_);
    float4 v = xr[t];
    float sum = v.x + v.y + v.z + v.w;
    float sq  = v.x*v.x + v.y*v.y + v.z*v.z + v.w*v.w;

    __shared__ float sh[64];
    int lane = t & 31, w = t >> 5;
    #pragma unroll
    for (int o = 16; o; o >>= 1) {
        sum += __shfl_xor_sync(~0u, sum, o);
        sq  += __shfl_xor_sync(~0u, sq,  o);
    }
    if (!lane) { sh[w] = sum; sh[w + 32] = sq; }
    __syncthreads();
    if (t < 32) {
        float s2 = (t < 8) ? sh[t]      : 0.0f;
        float q2 = (t < 8) ? sh[t + 32] : 0.0f;
        #pragma unroll
        for (int o = 4; o; o >>= 1) {
            s2 += __shfl_xor_sync(~0u, s2, o);
            q2 += __shfl_xor_sync(~0u, q2, o);
        }
        if (!t) { sh[0] = s2; sh[1] = q2; }
    }
    __syncthreads();
    float mean = sh[0] * (1.0f / D_);
    float var  = sh[1] * (1.0f / D_) - mean * mean;
    float inv  = rsqrtf(var + 1e-6f);

    float4 sv = ((const float4*)s)[t];
    float4 bv = ((const float4*)b)[t];
    float4 o4;
    o4.x = tf((v.x - mean) * inv * sv.x + bv.x);
    o4.y = tf((v.y - mean) * inv * sv.y + bv.y);
    o4.z = tf((v.z - mean) * inv * sv.z + bv.z);
    o4.w = tf((v.w - mean) * inv * sv.w + bv.w);
    ((float4*)(y + row * (size_t)D_))[t] = o4;
}

// ---------------- tf32 GEMM core: BK=32, 2-stage cp.async ----------------
// 128x128x32 tile, 256 threads = 8 warps (2x4), warp tile 64x32.
// A smem row-major [m][36] (4g+t bank perm); B smem [k][136] (8t+g perm).
// Operands pre-rounded to RNA-tf32 in gmem -> HW truncation is exact.
#define APAD 36
#define BPAD 136
#define GA2 (128*APAD)
#define GB2 (32*BPAD)
#define GEMM_SMEM ((2*GA2 + 2*GB2)*4)

struct GemmSmemPtrs { uint32_t as_b, bs_b; };

__device__ __forceinline__ void gemm_load_stage(
    uint32_t as_b, uint32_t bs_b, int st,
    const float* Ab, const float* Bb, int k0, int K, int N, int tid)
{
    uint32_t ad = as_b + (st * GA2) * 4;
    int ar = tid >> 1;
    const float* ag = Ab + (size_t)ar * K + k0;
    #pragma unroll
    for (int i = 0; i < 4; i++) {
        int c = (tid & 1) * 4 + i;
        cpa16(ad + (ar * APAD + c * 4) * 4, ag + c * 4);
    }
    uint32_t bd = bs_b + (st * GB2) * 4;
    int br = tid >> 3;
    const float* bg = Bb + (size_t)(k0 + br) * N;
    #pragma unroll
    for (int i = 0; i < 4; i++) {
        int c = (tid & 7) * 4 + i;
        cpa16(bd + (br * BPAD + c * 4) * 4, bg + c * 4);
    }
    asm volatile("cp.async.commit_group;");
}

__device__ __forceinline__ void gemm_compute_stage(
    const float* Asx, const float* Bsx, int wm, int wn, int g, int t,
    float acc[4][4][4])
{
    #pragma unroll
    for (int kk = 0; kk < 32; kk += 8) {
        uint32_t af[4][4], bf[4][2];
        #pragma unroll
        for (int mi = 0; mi < 4; mi++) {
            int m = wm + mi * 16 + g;
            af[mi][0] = __float_as_uint(Asx[(m    ) * APAD + kk + t    ]);
            af[mi][1] = __float_as_uint(Asx[(m + 8) * APAD + kk + t    ]);
            af[mi][2] = __float_as_uint(Asx[(m    ) * APAD + kk + t + 4]);
            af[mi][3] = __float_as_uint(Asx[(m + 8) * APAD + kk + t + 4]);
        }
        #pragma unroll
        for (int ni = 0; ni < 4; ni++) {
            int n = wn + ni * 8 + g;
            bf[ni][0] = __float_as_uint(Bsx[(kk + t    ) * BPAD + n]);
            bf[ni][1] = __float_as_uint(Bsx[(kk + t + 4) * BPAD + n]);
        }
        #pragma unroll
        for (int mi = 0; mi < 4; mi++)
            #pragma unroll
            for (int ni = 0; ni < 4; ni++)
                mma_tf32(acc[mi][ni], af[mi], bf[ni]);
    }
}

// EPI: 0 none, 1 +res, 2 round(gelu(+bias)), 3 +bias+res
template<int EPI>
__global__ __launch_bounds__(256, 2) void gemm_tc(
    const float* __restrict__ A, const float* __restrict__ Bm,
    float* __restrict__ C, int M, int N, int K,
    const float* __restrict__ bias, const float* __restrict__ res)
{
    extern __shared__ float sm[];
    float* As = sm;
    float* Bs = sm + 2 * GA2;
    uint32_t as_b = (uint32_t)__cvta_generic_to_shared(As);
    uint32_t bs_b = (uint32_t)__cvta_generic_to_shared(Bs);

    int tid = threadIdx.x, lane = tid & 31, wid = tid >> 5;
    int g = lane >> 2, t = lane & 3;
    int wm = (wid >> 2) * 64, wn = (wid & 3) * 32;

    const float* Ab = A  + (size_t)blockIdx.y * 128 * K;
    const float* Bb = Bm + (size_t)blockIdx.x * 128;

    float acc[4][4][4] = {};
    const int nk = K / 32;

    gemm_load_stage(as_b, bs_b, 0, Ab, Bb, 0, K, N, tid);
    for (int it = 0; it < nk; it++) {
        __syncthreads();   // prior readers of stage (it+1)&1 done
        if (it + 1 < nk) {
            gemm_load_stage(as_b, bs_b, (it + 1) & 1, Ab, Bb, (it + 1) * 32, K, N, tid);
            asm volatile("cp.async.wait_group 1;");
        } else {
            asm volatile("cp.async.wait_group 0;");
        }
        __syncthreads();
        gemm_compute_stage(As + (it & 1) * GA2, Bs + (it & 1) * GB2, wm, wn, g, t, acc);
    }

    #pragma unroll
    for (int mi = 0; mi < 4; mi++) {
        #pragma unroll
        for (int ci = 0; ci < 2; ci++) {
            int row = blockIdx.y * 128 + wm + mi * 16 + g + ci * 8;
            size_t roff = (size_t)row * N;
            #pragma unroll
            for (int ni = 0; ni < 4; ni++) {
                int col = blockIdx.x * 128 + wn + ni * 8 + 2 * t;
                float2 v = make_float2(acc[mi][ni][ci*2], acc[mi][ni][ci*2+1]);
                if (EPI == 1) {
                    float2 rv = *(const float2*)(res + roff + col);
                    v.x += rv.x; v.y += rv.y;
                } else if (EPI == 2) {
                    float2 bv = *(const float2*)(bias + col);
                    v.x = tf(gelu_f(v.x + bv.x)); v.y = tf(gelu_f(v.y + bv.y));
                } else if (EPI == 3) {
                    float2 bv = *(const float2*)(bias + col);
                    float2 rv = *(const float2*)(res + roff + col);
                    v.x += bv.x + rv.x; v.y += bv.y + rv.y;
                }
                *(float2*)(C + roff + col) = v;
            }
        }
    }
}

// fused QKV: grid (24, 32); bx>>3 selects weight/output, bx&7 selects col tile
__global__ __launch_bounds__(256, 2) void qkv_tc(
    const float* __restrict__ A, const float* __restrict__ W,   // concat rounded wq|wk|wv
    float* __restrict__ q, float* __restrict__ k, float* __restrict__ v)
{
    extern __shared__ float sm[];
    float* As = sm;
    float* Bs = sm + 2 * GA2;
    uint32_t as_b = (uint32_t)__cvta_generic_to_shared(As);
    uint32_t bs_b = (uint32_t)__cvta_generic_to_shared(Bs);

    int tid = threadIdx.x, lane = tid & 31, wid = tid >> 5;
    int g = lane >> 2, t = lane & 3;
    int wm = (wid >> 2) * 64, wn = (wid & 3) * 32;

    int wsel = blockIdx.x >> 3, nt = blockIdx.x & 7;
    const float* Ab = A + (size_t)blockIdx.y * 128 * D_;
    const float* Bb = W + (size_t)wsel * D_ * D_ + nt * 128;
    float* C = (wsel == 0 ? q : (wsel == 1 ? k : v));

    float acc[4][4][4] = {};
    const int nk = D_ / 32;

    gemm_load_stage(as_b, bs_b, 0, Ab, Bb, 0, D_, D_, tid);
    for (int it = 0; it < nk; it++) {
        __syncthreads();
        if (it + 1 < nk) {
            gemm_load_stage(as_b, bs_b, (it + 1) & 1, Ab, Bb, (it + 1) * 32, D_, D_, tid);
            asm volatile("cp.async.wait_group 1;");
        } else {
            asm volatile("cp.async.wait_group 0;");
        }
        __syncthreads();
        gemm_compute_stage(As + (it & 1) * GA2, Bs + (it & 1) * GB2, wm, wn, g, t, acc);
    }

    #pragma unroll
    for (int mi = 0; mi < 4; mi++) {
        #pragma unroll
        for (int ci = 0; ci < 2; ci++) {
            int row = blockIdx.y * 128 + wm + mi * 16 + g + ci * 8;
            size_t roff = (size_t)row * D_;
            #pragma unroll
            for (int ni = 0; ni < 4; ni++) {
                int col = nt * 128 + wn + ni * 8 + 2 * t;
                float2 o2 = make_float2(acc[mi][ni][ci*2], acc[mi][ni][ci*2+1]);
                *(float2*)(C + roff + col) = o2;
            }
        }
    }
}

// ---------------- RoPE ----------------
__global__ void rope_k(float* __restrict__ q, float* __restrict__ k)
{
    int i = blockIdx.x * blockDim.x + threadIdx.x;
    const int total = B_ * S_ * H_ * (DH_/2);
    if (i >= total) return;
    int p   = i & 31;
    int t   = i >> 5;
    int h   = t & 15;
    int row = t >> 4;
    int s   = row & (S_ - 1);

    float freq = 1.0f / powf(10000.0f, (float)(2*p) / (float)DH_);
    float ang  = (float)s * freq;
    float sn, cs;
    sincosf(ang, &sn, &cs);

    size_t off = (size_t)row * D_ + h * DH_ + 2 * p;
    float a = q[off], b = q[off+1];
    q[off]   = a * cs - b * sn;
    q[off+1] = a * sn + b * cs;
    a = k[off]; b = k[off+1];
    k[off]   = a * cs - b * sn;
    k[off+1] = a * sn + b * cs;
}

// ---------------- flash attention ----------------
#define KPAD 68
#define VPAD 72
#define PPAD 136
#define KS_FLOATS (2*128*KPAD)
#define VS_FLOATS (2*128*VPAD)
#define FLASH_SMEM ((KS_FLOATS + VS_FLOATS + 128*PPAD) * 4)

__global__ __launch_bounds__(256) void flash_k(
    const float* __restrict__ q, const float* __restrict__ k,
    const float* __restrict__ v, float* __restrict__ ctx)
{
    extern __shared__ float sm[];
    float* Ks = sm;
    float* Vs = sm + KS_FLOATS;
    float* Ps = sm + KS_FLOATS + VS_FLOATS;
    uint32_t ks_b = (uint32_t)__cvta_generic_to_shared(Ks);
    uint32_t vs_b = (uint32_t)__cvta_generic_to_shared(Vs);

    int tid = threadIdx.x, lane = tid & 31, wid = tid >> 5;
    int g = lane >> 2, t = lane & 3;
    int bh = blockIdx.y, b = bh >> 4, h = bh & 15;
    int q0 = blockIdx.x * 128;
    const float* qb = q + (size_t)b * S_ * D_ + h * DH_;
    const float* kb = k + (size_t)b * S_ * D_ + h * DH_;
    const float* vb = v + (size_t)b * S_ * D_ + h * DH_;

    {
        int row = tid >> 1, c0 = (tid & 1) * 32;
        const float* src = qb + (size_t)(q0 + row) * D_ + c0;
        #pragma unroll
        for (int i = 0; i < 8; i++) {
            float4 a = *(const float4*)(src + i * 4);
            Ps[(c0+i*4+0)*PPAD + row] = a.x;
            Ps[(c0+i*4+1)*PPAD + row] = a.y;
            Ps[(c0+i*4+2)*PPAD + row] = a.z;
            Ps[(c0+i*4+3)*PPAD + row] = a.w;
        }
    }

    {
        #pragma unroll
        for (int j = 0; j < 8; j++) {
            int id = tid + 256 * j;
            int r = id >> 4, c = id & 15;
            cpa16(ks_b + (r * KPAD + c * 4) * 4, kb + (size_t)r * D_ + c * 4);
            cpa16(vs_b + (r * VPAD + c * 4) * 4, vb + (size_t)r * D_ + c * 4);
        }
        asm volatile("cp.async.commit_group;");
    }
    __syncthreads();

    int m0 = wid * 16 + g;
    uint32_t qf[8][4];
    #pragma unroll
    for (int ks = 0; ks < 8; ks++) {
        qf[ks][0] = __float_as_uint(Ps[(8*ks+t  )*PPAD + m0    ]);
        qf[ks][1] = __float_as_uint(Ps[(8*ks+t  )*PPAD + m0 + 8]);
        qf[ks][2] = __float_as_uint(Ps[(8*ks+t+4)*PPAD + m0    ]);
        qf[ks][3] = __float_as_uint(Ps[(8*ks+t+4)*PPAD + m0 + 8]);
    }

    float m2[2] = {-1e30f, -1e30f};
    float l[2]  = {0.0f, 0.0f};
    float ao[8][4] = {};
    const float cs = 0.125f * 1.4426950408889634f;

    const int NT = S_ / 128;
    for (int it = 0; it < NT; it++) {
        int buf = it & 1;
        asm volatile("cp.async.wait_group 0;");
        __syncthreads();

        if (it + 1 < NT) {
            int kv0 = (it + 1) * 128;
            uint32_t kd = ks_b + (buf ^ 1) * 128 * KPAD * 4;
            uint32_t vd = vs_b + (buf ^ 1) * 128 * VPAD * 4;
            #pragma unroll
            for (int j = 0; j < 8; j++) {
                int id = tid + 256 * j;
                int r = id >> 4, c = id & 15;
                cpa16(kd + (r * KPAD + c * 4) * 4, kb + (size_t)(kv0 + r) * D_ + c * 4);
                cpa16(vd + (r * VPAD + c * 4) * 4, vb + (size_t)(kv0 + r) * D_ + c * 4);
            }
            asm volatile("cp.async.commit_group;");
        }

        const float* Kt = Ks + buf * 128 * KPAD;
        const float* Vt = Vs + buf * 128 * VPAD;

        float s[16][4] = {};
        #pragma unroll
        for (int ni = 0; ni < 16; ni++) {
            #pragma unroll
            for (int ks = 0; ks < 8; ks++) {
                uint32_t bf[2];
                bf[0] = __float_as_uint(Kt[(8*ni+g)*KPAD + 8*ks + t    ]);
                bf[1] = __float_as_uint(Kt[(8*ni+g)*KPAD + 8*ks + t + 4]);
                mma_tf32(s[ni], qf[ks], bf);
            }
        }

        float mx0 = -1e30f, mx1 = -1e30f;
        #pragma unroll
        for (int ni = 0; ni < 16; ni++) {
            mx0 = fmaxf(mx0, fmaxf(s[ni][0], s[ni][1]));
            mx1 = fmaxf(mx1, fmaxf(s[ni][2], s[ni][3]));
        }
        mx0 = fmaxf(mx0, __shfl_xor_sync(~0u, mx0, 1));
        mx0 = fmaxf(mx0, __shfl_xor_sync(~0u, mx0, 2));
        mx1 = fmaxf(mx1, __shfl_xor_sync(~0u, mx1, 1));
        mx1 = fmaxf(mx1, __shfl_xor_sync(~0u, mx1, 2));
        float nm0 = fmaxf(m2[0], mx0 * cs);
        float nm1 = fmaxf(m2[1], mx1 * cs);
        float cr0 = ex2f(m2[0] - nm0);
        float cr1 = ex2f(m2[1] - nm1);
        m2[0] = nm0; m2[1] = nm1;

        float sum0 = 0.0f, sum1 = 0.0f;
        #pragma unroll
        for (int ni = 0; ni < 16; ni++) {
            s[ni][0] = ex2f(fmaf(s[ni][0], cs, -nm0));
            s[ni][1] = ex2f(fmaf(s[ni][1], cs, -nm0));
            s[ni][2] = ex2f(fmaf(s[ni][2], cs, -nm1));
            s[ni][3] = ex2f(fmaf(s[ni][3], cs, -nm1));
            sum0 += s[ni][0] + s[ni][1];
            sum1 += s[ni][2] + s[ni][3];
        }
        sum0 += __shfl_xor_sync(~0u, sum0, 1);
        sum0 += __shfl_xor_sync(~0u, sum0, 2);
        sum1 += __shfl_xor_sync(~0u, sum1, 1);
        sum1 += __shfl_xor_sync(~0u, sum1, 2);
        l[0] = l[0] * cr0 + sum0;
        l[1] = l[1] * cr1 + sum1;

        #pragma unroll
        for (int ni = 0; ni < 8; ni++) {
            ao[ni][0] *= cr0; ao[ni][1] *= cr0;
            ao[ni][2] *= cr1; ao[ni][3] *= cr1;
        }

        #pragma unroll
        for (int ni = 0; ni < 16; ni++) {
            int col = 8 * ni + 2 * t;
            Ps[(col    )*PPAD + m0    ] = s[ni][0];
            Ps[(col + 1)*PPAD + m0    ] = s[ni][1];
            Ps[(col    )*PPAD + m0 + 8] = s[ni][2];
            Ps[(col + 1)*PPAD + m0 + 8] = s[ni][3];
        }
        __syncwarp();

        #pragma unroll
        for (int kst = 0; kst < 16; kst++) {
            uint32_t af[4];
            af[0] = __float_as_uint(Ps[(8*kst+t  )*PPAD + m0    ]);
            af[1] = __float_as_uint(Ps[(8*kst+t  )*PPAD + m0 + 8]);
            af[2] = __float_as_uint(Ps[(8*kst+t+4)*PPAD + m0    ]);
            af[3] = __float_as_uint(Ps[(8*kst+t+4)*PPAD + m0 + 8]);
            #pragma unroll
            for (int ni = 0; ni < 8; ni++) {
                uint32_t bf[2];
                bf[0] = __float_as_uint(Vt[(8*kst+t  )*VPAD + 8*ni + g]);
                bf[1] = __float_as_uint(Vt[(8*kst+t+4)*VPAD + 8*ni + g]);
                mma_tf32(ao[ni], af, bf);
            }
        }
    }

    // epilogue: normalize, RNA-round (ctx feeds gemm<1> A operand) and store
    float inv0 = 1.0f / l[0], inv1 = 1.0f / l[1];
    size_t base0 = ((size_t)b * S_ + q0 + m0) * D_ + h * DH_;
    size_t base1 = base0 + 8 * (size_t)D_;
    #pragma unroll
    for (int ni = 0; ni < 8; ni++) {
        int col = 8 * ni + 2 * t;
        float2 o0 = make_float2(tf(ao[ni][0] * inv0), tf(ao[ni][1] * inv0));
        float2 o1 = make_float2(tf(ao[ni][2] * inv1), tf(ao[ni][3] * inv1));
        *(float2*)(ctx + base0 + col) = o0;
        *(float2*)(ctx + base1 + col) = o1;
    }
}

// ---------------- launch ----------------
extern "C" void kernel_launch(void* const* d_in, const int* in_sizes, int n_in,
                              void* d_out, int out_size)
{
    const float* x    = (const float*)d_in[0];
    const float* ln1s = (const float*)d_in[1];
    const float* ln1b = (const float*)d_in[2];
    const float* wk   = (const float*)d_in[3];
    const float* wq   = (const float*)d_in[4];
    const float* wv   = (const float*)d_in[5];
    const float* wo   = (const float*)d_in[6];
    const float* ln2s = (const float*)d_in[7];
    const float* ln2b = (const float*)d_in[8];
    const float* w1   = (const float*)d_in[9];
    const float* b1   = (const float*)d_in[10];
    const float* w2   = (const float*)d_in[11];
    const float* b2   = (const float*)d_in[12];
    float* out = (float*)d_out;

    float *h, *q, *kb, *v, *ctx, *mlpin, *h2, *ff1, *wr;
    cudaGetSymbolAddress((void**)&h,     g_h);
    cudaGetSymbolAddress((void**)&q,     g_q);
    cudaGetSymbolAddress((void**)&kb,    g_k);
    cudaGetSymbolAddress((void**)&v,     g_v);
    cudaGetSymbolAddress((void**)&ctx,   g_ctx);
    cudaGetSymbolAddress((void**)&mlpin, g_mlpin);
    cudaGetSymbolAddress((void**)&h2,    g_h2);
    cudaGetSymbolAddress((void**)&ff1,   g_ff1);
    cudaGetSymbolAddress((void**)&wr,    g_wr);

    cudaFuncSetAttribute(flash_k,    cudaFuncAttributeMaxDynamicSharedMemorySize, FLASH_SMEM);
    cudaFuncSetAttribute(qkv_tc,     cudaFuncAttributeMaxDynamicSharedMemorySize, GEMM_SMEM);
    cudaFuncSetAttribute(gemm_tc<1>, cudaFuncAttributeMaxDynamicSharedMemorySize, GEMM_SMEM);
    cudaFuncSetAttribute(gemm_tc<2>, cudaFuncAttributeMaxDynamicSharedMemorySize, GEMM_SMEM);
    cudaFuncSetAttribute(gemm_tc<3>, cudaFuncAttributeMaxDynamicSharedMemorySize, GEMM_SMEM);

    // pre-round weights (RNA tf32) into scratch
    roundw_k<<<512, 256>>>(wq, wr + WR_WQ, (D_*D_)/4);
    roundw_k<<<512, 256>>>(wk, wr + WR_WK, (D_*D_)/4);
    roundw_k<<<512, 256>>>(wv, wr + WR_WV, (D_*D_)/4);
    roundw_k<<<512, 256>>>(wo, wr + WR_WO, (D_*D_)/4);
    roundw_k<<<512, 256>>>(w1, wr + WR_W1, (D_*M_)/4);
    roundw_k<<<512, 256>>>(w2, wr + WR_W2, (M_*D_)/4);

    layernorm_k<<<R_, 256>>>(x, ln1s, ln1b, h);
    qkv_tc<<<dim3(24, R_/128), 256, GEMM_SMEM>>>(h, wr + WR_WQ, q, kb, v);
    {
        int total = B_ * S_ * H_ * (DH_/2);
        rope_k<<<(total + 255) / 256, 256>>>(q, kb);
    }
    flash_k<<<dim3(S_/128, B_*H_), 256, FLASH_SMEM>>>(q, kb, v, ctx);
    gemm_tc<1><<<dim3(D_/128, R_/128), 256, GEMM_SMEM>>>(ctx, wr + WR_WO, mlpin, R_, D_, D_, nullptr, x);
    layernorm_k<<<R_, 256>>>(mlpin, ln2s, ln2b, h2);
    gemm_tc<2><<<dim3(M_/128, R_/128), 256, GEMM_SMEM>>>(h2,  wr + WR_W1, ff1, R_, M_, D_, b1, nullptr);
    gemm_tc<3><<<dim3(D_/128, R_/128), 256, GEMM_SMEM>>>(ff1, wr + WR_W2, out, R_, D_, M_, b2, mlpin);
}

// round 17
// speedup vs baseline: 1.1930x; 1.1930x over previous
#include <cuda_runtime.h>
#include <math.h>
#include <stdint.h>

// Problem dims
#define B_  2
#define S_  2048
#define D_  1024
#define H_  16
#define DH_ 64
#define M_  4096
#define R_  (B_*S_)   // 4096 rows total

// ---------------- scratch (__device__ globals: allocation-free) ----------------
__device__ float g_h    [(size_t)R_*D_];
__device__ float g_q    [(size_t)R_*D_];
__device__ float g_k    [(size_t)R_*D_];
__device__ float g_v    [(size_t)R_*D_];
__device__ float g_ctx  [(size_t)R_*D_];
__device__ float g_mlpin[(size_t)R_*D_];
__device__ float g_h2   [(size_t)R_*D_];
__device__ float g_ff1  [(size_t)R_*M_];
// rounded weights: wq(1M) wk(1M) wv(1M) wo(1M) w1(4M) w2(4M) = 12M floats
__device__ float g_wr   [(size_t)12*1024*1024];

#define WR_WQ 0
#define WR_WK (1024*1024)
#define WR_WV (2*1024*1024)
#define WR_WO (3*1024*1024)
#define WR_W1 (4*1024*1024)
#define WR_W2 (8*1024*1024)

// ---------------- helpers ----------------
__device__ __forceinline__ float gelu_f(float x){
    const float c = 0.7978845608028654f;  // sqrt(2/pi)
    return 0.5f * x * (1.0f + tanhf(c * (x + 0.044715f * x * x * x)));
}

__device__ __forceinline__ float tf(float x){
    uint32_t u;
    asm("cvt.rna.tf32.f32 %0, %1;" : "=r"(u) : "f"(x));
    return __uint_as_float(u);
}

__device__ __forceinline__ float ex2f(float x){
    float y; asm("ex2.approx.ftz.f32 %0, %1;" : "=f"(y) : "f"(x)); return y;
}

__device__ __forceinline__ void mma_tf32(float* c, const uint32_t* a, const uint32_t* b){
    asm volatile(
        "mma.sync.aligned.m16n8k8.row.col.f32.tf32.tf32.f32 "
        "{%0,%1,%2,%3}, {%4,%5,%6,%7}, {%8,%9}, {%0,%1,%2,%3};"
        : "+f"(c[0]), "+f"(c[1]), "+f"(c[2]), "+f"(c[3])
        : "r"(a[0]), "r"(a[1]), "r"(a[2]), "r"(a[3]), "r"(b[0]), "r"(b[1]));
}

__device__ __forceinline__ void cpa16(uint32_t dst, const void* src){
    asm volatile("cp.async.cg.shared.global [%0], [%1], 16;" :: "r"(dst), "l"(src));
}

// ---------------- fused weight pre-round (RNA tf32), one launch ----------------
// dest layout (float4 units): [wq 256K][wk 256K][wv 256K][wo 256K][w1 1M][w2 1M]
__global__ __launch_bounds__(256) void roundw_all(
    const float* __restrict__ wq, const float* __restrict__ wk,
    const float* __restrict__ wv, const float* __restrict__ wo,
    const float* __restrict__ w1, const float* __restrict__ w2,
    float* __restrict__ d)
{
    const int n4 = 3 * 1024 * 1024;
    int i = blockIdx.x * blockDim.x + threadIdx.x;
    int stride = gridDim.x * blockDim.x;
    for (; i < n4; i += stride) {
        const float4* src; int j;
        if      (i < (1<<18))      { src = (const float4*)wq; j = i; }
        else if (i < (2<<18))      { src = (const float4*)wk; j = i - (1<<18); }
        else if (i < (3<<18))      { src = (const float4*)wv; j = i - (2<<18); }
        else if (i < (4<<18))      { src = (const float4*)wo; j = i - (3<<18); }
        else if (i < (4<<18)+(1<<20)) { src = (const float4*)w1; j = i - (4<<18); }
        else                       { src = (const float4*)w2; j = i - (4<<18) - (1<<20); }
        float4 v = src[j];
        v.x = tf(v.x); v.y = tf(v.y); v.z = tf(v.z); v.w = tf(v.w);
        ((float4*)d)[i] = v;
    }
}

// ---------------- LayerNorm (output RNA-rounded: feeds MMAs only) ----------------
__global__ __launch_bounds__(256) void layernorm_k(
    const float* __restrict__ x, const float* __restrict__ s,
    const float* __restrict__ b, float* __restrict__ y)
{
    size_t row = blockIdx.x;
    int t = threadIdx.x;
    const float4* xr = (const float4*)(x + row * (size_t)D_);
    float4 v = xr[t];
    float sum = v.x + v.y + v.z + v.w;
    float sq  = v.x*v.x + v.y*v.y + v.z*v.z + v.w*v.w;

    __shared__ float sh[64];
    int lane = t & 31, w = t >> 5;
    #pragma unroll
    for (int o = 16; o; o >>= 1) {
        sum += __shfl_xor_sync(~0u, sum, o);
        sq  += __shfl_xor_sync(~0u, sq,  o);
    }
    if (!lane) { sh[w] = sum; sh[w + 32] = sq; }
    __syncthreads();
    if (t < 32) {
        float s2 = (t < 8) ? sh[t]      : 0.0f;
        float q2 = (t < 8) ? sh[t + 32] : 0.0f;
        #pragma unroll
        for (int o = 4; o; o >>= 1) {
            s2 += __shfl_xor_sync(~0u, s2, o);
            q2 += __shfl_xor_sync(~0u, q2, o);
        }
        if (!t) { sh[0] = s2; sh[1] = q2; }
    }
    __syncthreads();
    float mean = sh[0] * (1.0f / D_);
    float var  = sh[1] * (1.0f / D_) - mean * mean;
    float inv  = rsqrtf(var + 1e-6f);

    float4 sv = ((const float4*)s)[t];
    float4 bv = ((const float4*)b)[t];
    float4 o4;
    o4.x = tf((v.x - mean) * inv * sv.x + bv.x);
    o4.y = tf((v.y - mean) * inv * sv.y + bv.y);
    o4.z = tf((v.z - mean) * inv * sv.z + bv.z);
    o4.w = tf((v.w - mean) * inv * sv.w + bv.w);
    ((float4*)(y + row * (size_t)D_))[t] = o4;
}

// ---------------- tf32 GEMM core: BK=16, 4-stage cp.async ring ----------------
// 128x128x16 tile, 256 threads = 8 warps (2x4), warp tile 64x32.
// A smem row-major [m][20] (bank perm 20g+t); B smem [k][136] (8t+g perm).
// Operands pre-rounded to RNA-tf32 in gmem -> HW truncation is exact.
#define APAD 20
#define BPAD 136
#define GA_STG (128*APAD)   // 2560 floats
#define GB_STG (16*BPAD)    // 2176 floats
#define NSTG 4
#define GEMM_SMEM ((NSTG*GA_STG + NSTG*GB_STG)*4)

__device__ __forceinline__ void gemm_load_stage(
    uint32_t as_b, uint32_t bs_b, int st,
    const float* Ab, const float* Bb, int k0, int K, int N, int tid)
{
    uint32_t ad = as_b + (st * GA_STG) * 4;
    int ar  = tid >> 1;
    int ac0 = (tid & 1) * 2;
    const float* ag = Ab + (size_t)ar * K + k0;
    cpa16(ad + (ar * APAD + (ac0    ) * 4) * 4, ag + (ac0    ) * 4);
    cpa16(ad + (ar * APAD + (ac0 + 1) * 4) * 4, ag + (ac0 + 1) * 4);
    uint32_t bd = bs_b + (st * GB_STG) * 4;
    int br  = tid >> 4;
    int bc0 = tid & 15;
    const float* bg = Bb + (size_t)(k0 + br) * N;
    cpa16(bd + (br * BPAD + (bc0     ) * 4) * 4, bg + (bc0     ) * 4);
    cpa16(bd + (br * BPAD + (bc0 + 16) * 4) * 4, bg + (bc0 + 16) * 4);
}

__device__ __forceinline__ void gemm_compute_stage(
    const float* Asx, const float* Bsx, int wm, int wn, int g, int t,
    float acc[4][4][4])
{
    #pragma unroll
    for (int kk = 0; kk < 16; kk += 8) {
        uint32_t af[4][4], bf[4][2];
        #pragma unroll
        for (int mi = 0; mi < 4; mi++) {
            int m = wm + mi * 16 + g;
            af[mi][0] = __float_as_uint(Asx[(m    ) * APAD + kk + t    ]);
            af[mi][1] = __float_as_uint(Asx[(m + 8) * APAD + kk + t    ]);
            af[mi][2] = __float_as_uint(Asx[(m    ) * APAD + kk + t + 4]);
            af[mi][3] = __float_as_uint(Asx[(m + 8) * APAD + kk + t + 4]);
        }
        #pragma unroll
        for (int ni = 0; ni < 4; ni++) {
            int n = wn + ni * 8 + g;
            bf[ni][0] = __float_as_uint(Bsx[(kk + t    ) * BPAD + n]);
            bf[ni][1] = __float_as_uint(Bsx[(kk + t + 4) * BPAD + n]);
        }
        #pragma unroll
        for (int mi = 0; mi < 4; mi++)
            #pragma unroll
            for (int ni = 0; ni < 4; ni++)
                mma_tf32(acc[mi][ni], af[mi], bf[ni]);
    }
}

// Main loop shared by all GEMM kernels. One barrier per iteration; a group is
// committed EVERY iteration so wait_group 2 always means "stage it is resident".
#define GEMM_MAINLOOP(Ab, Bb, K, N)                                          \
    {                                                                        \
        _Pragma("unroll")                                                    \
        for (int p = 0; p < 3; p++) {                                        \
            if (p < nk) gemm_load_stage(as_b, bs_b, p, Ab, Bb, p*16, K, N, tid); \
            asm volatile("cp.async.commit_group;");                          \
        }                                                                    \
        for (int it = 0; it < nk; it++) {                                    \
            asm volatile("cp.async.wait_group 2;");                          \
            __syncthreads();                                                 \
            if (it + 3 < nk)                                                 \
                gemm_load_stage(as_b, bs_b, (it+3) & 3, Ab, Bb, (it+3)*16, K, N, tid); \
            asm volatile("cp.async.commit_group;");                          \
            gemm_compute_stage(As + (it & 3) * GA_STG, Bs + (it & 3) * GB_STG, \
                               wm, wn, g, t, acc);                           \
        }                                                                    \
    }

// EPI: 1 +res, 2 round(gelu(+bias)), 3 +bias+res
template<int EPI>
__global__ __launch_bounds__(256, 2) void gemm_tc(
    const float* __restrict__ A, const float* __restrict__ Bm,
    float* __restrict__ C, int M, int N, int K,
    const float* __restrict__ bias, const float* __restrict__ res)
{
    extern __shared__ float sm[];
    float* As = sm;
    float* Bs = sm + NSTG * GA_STG;
    uint32_t as_b = (uint32_t)__cvta_generic_to_shared(As);
    uint32_t bs_b = (uint32_t)__cvta_generic_to_shared(Bs);

    int tid = threadIdx.x, lane = tid & 31, wid = tid >> 5;
    int g = lane >> 2, t = lane & 3;
    int wm = (wid >> 2) * 64, wn = (wid & 3) * 32;

    const float* Ab = A  + (size_t)blockIdx.y * 128 * K;
    const float* Bb = Bm + (size_t)blockIdx.x * 128;

    float acc[4][4][4] = {};
    const int nk = K / 16;

    GEMM_MAINLOOP(Ab, Bb, K, N)

    #pragma unroll
    for (int mi = 0; mi < 4; mi++) {
        #pragma unroll
        for (int ci = 0; ci < 2; ci++) {
            int row = blockIdx.y * 128 + wm + mi * 16 + g + ci * 8;
            size_t roff = (size_t)row * N;
            #pragma unroll
            for (int ni = 0; ni < 4; ni++) {
                int col = blockIdx.x * 128 + wn + ni * 8 + 2 * t;
                float2 v = make_float2(acc[mi][ni][ci*2], acc[mi][ni][ci*2+1]);
                if (EPI == 1) {
                    float2 rv = *(const float2*)(res + roff + col);
                    v.x += rv.x; v.y += rv.y;
                } else if (EPI == 2) {
                    float2 bv = *(const float2*)(bias + col);
                    v.x = tf(gelu_f(v.x + bv.x)); v.y = tf(gelu_f(v.y + bv.y));
                } else if (EPI == 3) {
                    float2 bv = *(const float2*)(bias + col);
                    float2 rv = *(const float2*)(res + roff + col);
                    v.x += bv.x + rv.x; v.y += bv.y + rv.y;
                }
                *(float2*)(C + roff + col) = v;
            }
        }
    }
}

// fused QKV + RoPE: grid (24, 32); bx>>3 selects weight/output, bx&7 col tile.
// RoPE applied inline in epilogue for q,k (float2 at even col = rotation pair);
// q,k,v all RNA-rounded (they feed flash MMAs).
__global__ __launch_bounds__(256, 2) void qkv_tc(
    const float* __restrict__ A, const float* __restrict__ W,   // rounded wq|wk|wv
    float* __restrict__ q, float* __restrict__ k, float* __restrict__ v)
{
    extern __shared__ float sm[];
    float* As = sm;
    float* Bs = sm + NSTG * GA_STG;
    uint32_t as_b = (uint32_t)__cvta_generic_to_shared(As);
    uint32_t bs_b = (uint32_t)__cvta_generic_to_shared(Bs);

    int tid = threadIdx.x, lane = tid & 31, wid = tid >> 5;
    int g = lane >> 2, t = lane & 3;
    int wm = (wid >> 2) * 64, wn = (wid & 3) * 32;

    int wsel = blockIdx.x >> 3, nt = blockIdx.x & 7;
    const float* Ab = A + (size_t)blockIdx.y * 128 * D_;
    const float* Bb = W + (size_t)wsel * D_ * D_ + nt * 128;
    float* C = (wsel == 0 ? q : (wsel == 1 ? k : v));

    float acc[4][4][4] = {};
    const int nk = D_ / 16;

    GEMM_MAINLOOP(Ab, Bb, D_, D_)

    #pragma unroll
    for (int mi = 0; mi < 4; mi++) {
        #pragma unroll
        for (int ci = 0; ci < 2; ci++) {
            int row = blockIdx.y * 128 + wm + mi * 16 + g + ci * 8;
            size_t roff = (size_t)row * D_;
            int s = row & (S_ - 1);
            #pragma unroll
            for (int ni = 0; ni < 4; ni++) {
                int col = nt * 128 + wn + ni * 8 + 2 * t;   // even
                float2 o2 = make_float2(acc[mi][ni][ci*2], acc[mi][ni][ci*2+1]);
                if (wsel < 2) {
                    // rope: pair index within head = (col&63)/2
                    float e = (float)(col & 63) * (1.0f / 64.0f);
                    float freq = 1.0f / powf(10000.0f, e);
                    float sn, cs;
                    sincosf((float)s * freq, &sn, &cs);
                    float a = o2.x, b = o2.y;
                    o2.x = a * cs - b * sn;
                    o2.y = a * sn + b * cs;
                }
                o2.x = tf(o2.x); o2.y = tf(o2.y);
                *(float2*)(C + roff + col) = o2;
            }
        }
    }
}

// ---------------- flash attention ----------------
#define KPAD 68
#define VPAD 72
#define PPAD 136
#define KS_FLOATS (2*128*KPAD)
#define VS_FLOATS (2*128*VPAD)
#define FLASH_SMEM ((KS_FLOATS + VS_FLOATS + 128*PPAD) * 4)

__global__ __launch_bounds__(256) void flash_k(
    const float* __restrict__ q, const float* __restrict__ k,
    const float* __restrict__ v, float* __restrict__ ctx)
{
    extern __shared__ float sm[];
    float* Ks = sm;
    float* Vs = sm + KS_FLOATS;
    float* Ps = sm + KS_FLOATS + VS_FLOATS;
    uint32_t ks_b = (uint32_t)__cvta_generic_to_shared(Ks);
    uint32_t vs_b = (uint32_t)__cvta_generic_to_shared(Vs);

    int tid = threadIdx.x, lane = tid & 31, wid = tid >> 5;
    int g = lane >> 2, t = lane & 3;
    int bh = blockIdx.y, b = bh >> 4, h = bh & 15;
    int q0 = blockIdx.x * 128;
    const float* qb = q + (size_t)b * S_ * D_ + h * DH_;
    const float* kb = k + (size_t)b * S_ * D_ + h * DH_;
    const float* vb = v + (size_t)b * S_ * D_ + h * DH_;

    {
        int row = tid >> 1, c0 = (tid & 1) * 32;
        const float* src = qb + (size_t)(q0 + row) * D_ + c0;
        #pragma unroll
        for (int i = 0; i < 8; i++) {
            float4 a = *(const float4*)(src + i * 4);
            Ps[(c0+i*4+0)*PPAD + row] = a.x;
            Ps[(c0+i*4+1)*PPAD + row] = a.y;
            Ps[(c0+i*4+2)*PPAD + row] = a.z;
            Ps[(c0+i*4+3)*PPAD + row] = a.w;
        }
    }

    {
        #pragma unroll
        for (int j = 0; j < 8; j++) {
            int id = tid + 256 * j;
            int r = id >> 4, c = id & 15;
            cpa16(ks_b + (r * KPAD + c * 4) * 4, kb + (size_t)r * D_ + c * 4);
            cpa16(vs_b + (r * VPAD + c * 4) * 4, vb + (size_t)r * D_ + c * 4);
        }
        asm volatile("cp.async.commit_group;");
    }
    __syncthreads();

    int m0 = wid * 16 + g;
    uint32_t qf[8][4];
    #pragma unroll
    for (int ks = 0; ks < 8; ks++) {
        qf[ks][0] = __float_as_uint(Ps[(8*ks+t  )*PPAD + m0    ]);
        qf[ks][1] = __float_as_uint(Ps[(8*ks+t  )*PPAD + m0 + 8]);
        qf[ks][2] = __float_as_uint(Ps[(8*ks+t+4)*PPAD + m0    ]);
        qf[ks][3] = __float_as_uint(Ps[(8*ks+t+4)*PPAD + m0 + 8]);
    }

    float m2[2] = {-1e30f, -1e30f};
    float l[2]  = {0.0f, 0.0f};
    float ao[8][4] = {};
    const float cs = 0.125f * 1.4426950408889634f;

    const int NT = S_ / 128;
    for (int it = 0; it < NT; it++) {
        int buf = it & 1;
        asm volatile("cp.async.wait_group 0;");
        __syncthreads();

        if (it + 1 < NT) {
            int kv0 = (it + 1) * 128;
            uint32_t kd = ks_b + (buf ^ 1) * 128 * KPAD * 4;
            uint32_t vd = vs_b + (buf ^ 1) * 128 * VPAD * 4;
            #pragma unroll
            for (int j = 0; j < 8; j++) {
                int id = tid + 256 * j;
                int r = id >> 4, c = id & 15;
                cpa16(kd + (r * KPAD + c * 4) * 4, kb + (size_t)(kv0 + r) * D_ + c * 4);
                cpa16(vd + (r * VPAD + c * 4) * 4, vb + (size_t)(kv0 + r) * D_ + c * 4);
            }
            asm volatile("cp.async.commit_group;");
        }

        const float* Kt = Ks + buf * 128 * KPAD;
        const float* Vt = Vs + buf * 128 * VPAD;

        float s[16][4] = {};
        #pragma unroll
        for (int ni = 0; ni < 16; ni++) {
            #pragma unroll
            for (int ks = 0; ks < 8; ks++) {
                uint32_t bf[2];
                bf[0] = __float_as_uint(Kt[(8*ni+g)*KPAD + 8*ks + t    ]);
                bf[1] = __float_as_uint(Kt[(8*ni+g)*KPAD + 8*ks + t + 4]);
                mma_tf32(s[ni], qf[ks], bf);
            }
        }

        float mx0 = -1e30f, mx1 = -1e30f;
        #pragma unroll
        for (int ni = 0; ni < 16; ni++) {
            mx0 = fmaxf(mx0, fmaxf(s[ni][0], s[ni][1]));
            mx1 = fmaxf(mx1, fmaxf(s[ni][2], s[ni][3]));
        }
        mx0 = fmaxf(mx0, __shfl_xor_sync(~0u, mx0, 1));
        mx0 = fmaxf(mx0, __shfl_xor_sync(~0u, mx0, 2));
        mx1 = fmaxf(mx1, __shfl_xor_sync(~0u, mx1, 1));
        mx1 = fmaxf(mx1, __shfl_xor_sync(~0u, mx1, 2));
        float nm0 = fmaxf(m2[0], mx0 * cs);
        float nm1 = fmaxf(m2[1], mx1 * cs);
        float cr0 = ex2f(m2[0] - nm0);
        float cr1 = ex2f(m2[1] - nm1);
        m2[0] = nm0; m2[1] = nm1;

        float sum0 = 0.0f, sum1 = 0.0f;
        #pragma unroll
        for (int ni = 0; ni < 16; ni++) {
            s[ni][0] = ex2f(fmaf(s[ni][0], cs, -nm0));
            s[ni][1] = ex2f(fmaf(s[ni][1], cs, -nm0));
            s[ni][2] = ex2f(fmaf(s[ni][2], cs, -nm1));
            s[ni][3] = ex2f(fmaf(s[ni][3], cs, -nm1));
            sum0 += s[ni][0] + s[ni][1];
            sum1 += s[ni][2] + s[ni][3];
        }
        sum0 += __shfl_xor_sync(~0u, sum0, 1);
        sum0 += __shfl_xor_sync(~0u, sum0, 2);
        sum1 += __shfl_xor_sync(~0u, sum1, 1);
        sum1 += __shfl_xor_sync(~0u, sum1, 2);
        l[0] = l[0] * cr0 + sum0;
        l[1] = l[1] * cr1 + sum1;

        #pragma unroll
        for (int ni = 0; ni < 8; ni++) {
            ao[ni][0] *= cr0; ao[ni][1] *= cr0;
            ao[ni][2] *= cr1; ao[ni][3] *= cr1;
        }

        #pragma unroll
        for (int ni = 0; ni < 16; ni++) {
            int col = 8 * ni + 2 * t;
            Ps[(col    )*PPAD + m0    ] = s[ni][0];
            Ps[(col + 1)*PPAD + m0    ] = s[ni][1];
            Ps[(col    )*PPAD + m0 + 8] = s[ni][2];
            Ps[(col + 1)*PPAD + m0 + 8] = s[ni][3];
        }
        __syncwarp();

        #pragma unroll
        for (int kst = 0; kst < 16; kst++) {
            uint32_t af[4];
            af[0] = __float_as_uint(Ps[(8*kst+t  )*PPAD + m0    ]);
            af[1] = __float_as_uint(Ps[(8*kst+t  )*PPAD + m0 + 8]);
            af[2] = __float_as_uint(Ps[(8*kst+t+4)*PPAD + m0    ]);
            af[3] = __float_as_uint(Ps[(8*kst+t+4)*PPAD + m0 + 8]);
            #pragma unroll
            for (int ni = 0; ni < 8; ni++) {
                uint32_t bf[2];
                bf[0] = __float_as_uint(Vt[(8*kst+t  )*VPAD + 8*ni + g]);
                bf[1] = __float_as_uint(Vt[(8*kst+t+4)*VPAD + 8*ni + g]);
                mma_tf32(ao[ni], af, bf);
            }
        }
    }

    // epilogue: normalize, RNA-round (ctx feeds gemm<1> A operand) and store
    float inv0 = 1.0f / l[0], inv1 = 1.0f / l[1];
    size_t base0 = ((size_t)b * S_ + q0 + m0) * D_ + h * DH_;
    size_t base1 = base0 + 8 * (size_t)D_;
    #pragma unroll
    for (int ni = 0; ni < 8; ni++) {
        int col = 8 * ni + 2 * t;
        float2 o0 = make_float2(tf(ao[ni][0] * inv0), tf(ao[ni][1] * inv0));
        float2 o1 = make_float2(tf(ao[ni][2] * inv1), tf(ao[ni][3] * inv1));
        *(float2*)(ctx + base0 + col) = o0;
        *(float2*)(ctx + base1 + col) = o1;
    }
}

// ---------------- launch ----------------
extern "C" void kernel_launch(void* const* d_in, const int* in_sizes, int n_in,
                              void* d_out, int out_size)
{
    const float* x    = (const float*)d_in[0];
    const float* ln1s = (const float*)d_in[1];
    const float* ln1b = (const float*)d_in[2];
    const float* wk   = (const float*)d_in[3];
    const float* wq   = (const float*)d_in[4];
    const float* wv   = (const float*)d_in[5];
    const float* wo   = (const float*)d_in[6];
    const float* ln2s = (const float*)d_in[7];
    const float* ln2b = (const float*)d_in[8];
    const float* w1   = (const float*)d_in[9];
    const float* b1   = (const float*)d_in[10];
    const float* w2   = (const float*)d_in[11];
    const float* b2   = (const float*)d_in[12];
    float* out = (float*)d_out;

    float *h, *q, *kb, *v, *ctx, *mlpin, *h2, *ff1, *wr;
    cudaGetSymbolAddress((void**)&h,     g_h);
    cudaGetSymbolAddress((void**)&q,     g_q);
    cudaGetSymbolAddress((void**)&kb,    g_k);
    cudaGetSymbolAddress((void**)&v,     g_v);
    cudaGetSymbolAddress((void**)&ctx,   g_ctx);
    cudaGetSymbolAddress((void**)&mlpin, g_mlpin);
    cudaGetSymbolAddress((void**)&h2,    g_h2);
    cudaGetSymbolAddress((void**)&ff1,   g_ff1);
    cudaGetSymbolAddress((void**)&wr,    g_wr);

    cudaFuncSetAttribute(flash_k,    cudaFuncAttributeMaxDynamicSharedMemorySize, FLASH_SMEM);
    cudaFuncSetAttribute(qkv_tc,     cudaFuncAttributeMaxDynamicSharedMemorySize, GEMM_SMEM);
    cudaFuncSetAttribute(gemm_tc<1>, cudaFuncAttributeMaxDynamicSharedMemorySize, GEMM_SMEM);
    cudaFuncSetAttribute(gemm_tc<2>, cudaFuncAttributeMaxDynamicSharedMemorySize, GEMM_SMEM);
    cudaFuncSetAttribute(gemm_tc<3>, cudaFuncAttributeMaxDynamicSharedMemorySize, GEMM_SMEM);

    // pre-round all weights (RNA tf32) into scratch: ONE launch
    roundw_all<<<3072, 256>>>(wq, wk, wv, wo, w1, w2, wr);

    layernorm_k<<<R_, 256>>>(x, ln1s, ln1b, h);
    qkv_tc<<<dim3(24, R_/128), 256, GEMM_SMEM>>>(h, wr + WR_WQ, q, kb, v);
    flash_k<<<dim3(S_/128, B_*H_), 256, FLASH_SMEM>>>(q, kb, v, ctx);
    gemm_tc<1><<<dim3(D_/128, R_/128), 256, GEMM_SMEM>>>(ctx, wr + WR_WO, mlpin, R_, D_, D_, nullptr, x);
    layernorm_k<<<R_, 256>>>(mlpin, ln2s, ln2b, h2);
    gemm_tc<2><<<dim3(M_/128, R_/128), 256, GEMM_SMEM>>>(h2,  wr + WR_W1, ff1, R_, M_, D_, b1, nullptr);
    gemm_tc<3><<<dim3(D_/128, R_/128), 256, GEMM_SMEM>>>(ff1, wr + WR_W2, out, R_, D_, M_, b2, mlpin);
}